// round 4
// baseline (speedup 1.0000x reference)
#include <cuda_runtime.h>
#include <cstdint>

// MeanAggregatorHead: out[b, :] = (1/K) * sum_k embed_table[neigh_idx[b,k], :]
// B=100000, K=32, N=500000, D=128, fp32 table, int32 indices.
//
// P=4 table-chunked passes: each launch gathers only rows in [lo, hi)
// (64MB chunk) so in-chunk random reads hit L2 (~126MB). Out partials
// (51MB) + idx (13MB) also fit alongside the chunk. Irreducible L2 gather
// traffic = 1.64GB; goal is L2-bound at ~20TB/s empirical peak.

constexpr int K = 32;
constexpr int D = 128;

__device__ __forceinline__ void st_cs_f4(float4* p, float4 v) {
    asm volatile("st.global.cs.v4.f32 [%0], {%1,%2,%3,%4};"
                 :: "l"(p), "f"(v.x), "f"(v.y), "f"(v.z), "f"(v.w) : "memory");
}

template <int LAST>
__global__ __launch_bounds__(256) void mean_agg_pass(
    const float* __restrict__ tab,
    const int*   __restrict__ idx,
    float* __restrict__ out,
    int B, int lo, int hi, int residual)
{
    int gtid = blockIdx.x * blockDim.x + threadIdx.x;
    int warp = gtid >> 5;
    int lane = gtid & 31;
    if (warp >= B) return;

    // One coalesced 4B index load per lane; broadcast via shfl in the loop.
    int my_idx = __ldg(&idx[(size_t)warp * K + lane]);

    float4 acc = make_float4(0.f, 0.f, 0.f, 0.f);

    #pragma unroll
    for (int k = 0; k < K; ++k) {
        int r = __shfl_sync(0xffffffffu, my_idx, k);
        // Warp-uniform predicate: whole warp takes or skips the load together.
        if (r >= lo && r < hi) {
            const float4* row = reinterpret_cast<const float4*>(tab + (size_t)r * D);
            float4 v = __ldg(&row[lane]);   // 512B coalesced row per warp
            acc.x += v.x; acc.y += v.y; acc.z += v.z; acc.w += v.w;
        }
    }

    float4* op = reinterpret_cast<float4*>(out + (size_t)warp * D);
    if (residual) {
        float4 p = op[lane];                // partial from previous pass (L2-hit)
        acc.x += p.x; acc.y += p.y; acc.z += p.z; acc.w += p.w;
    }

    if (LAST) {
        const float s = 1.0f / (float)K;
        acc.x *= s; acc.y *= s; acc.z *= s; acc.w *= s;
        st_cs_f4(&op[lane], acc);           // streaming: out never re-read
    } else {
        op[lane] = acc;                     // keep partial L2-resident
    }
}

extern "C" void kernel_launch(void* const* d_in, const int* in_sizes, int n_in,
                              void* d_out, int out_size)
{
    // Identify inputs by element count (robust to metadata ordering):
    // embed_table: N*D = 64,000,000 ; neigh_idx: B*K = 3,200,000 ; num_sample: 1
    long long max_sz = -1, mid_sz = -1;
    int ti = 0, ii = 1;
    for (int i = 0; i < n_in; ++i)
        if (in_sizes[i] > max_sz) { max_sz = in_sizes[i]; ti = i; }
    for (int i = 0; i < n_in; ++i)
        if (i != ti && in_sizes[i] > mid_sz) { mid_sz = in_sizes[i]; ii = i; }

    const float* tab = (const float*)d_in[ti];
    const int*   idx = (const int*)d_in[ii];
    float*       out = (float*)d_out;

    int B = out_size / D;                    // 100000
    int N = (int)(max_sz / D);               // 500000 table rows

    constexpr int P = 4;                     // 125000 rows = 64MB per chunk

    int threads = 256;
    long long total_threads = (long long)B * 32;
    int blocks = (int)((total_threads + threads - 1) / threads);

    int chunk = (N + P - 1) / P;
    for (int p = 0; p < P; ++p) {
        int lo = p * chunk;
        int hi = (p + 1 < P) ? lo + chunk : N;
        if (p + 1 < P)
            mean_agg_pass<0><<<blocks, threads>>>(tab, idx, out, B, lo, hi, p > 0);
        else
            mean_agg_pass<1><<<blocks, threads>>>(tab, idx, out, B, lo, hi, p > 0);
    }
}

// round 5
// speedup vs baseline: 1.0266x; 1.0266x over previous
#include <cuda_runtime.h>
#include <cstdint>

// MeanAggregatorHead: out[b, :] = (1/K) * sum_k embed_table[neigh_idx[b,k], :]
// B=100000, K=32, N=500000, D=128, fp32 table, int32 indices.
//
// Model (validated on R2-R4): t = max(L2_bytes/11.3TB/s, DRAM_bytes/6.7TB/s).
// Gather L2 traffic (1.64GB) is irreducible; only single-pass minimizes L2
// bytes (1.70GB -> 150us floor). Fix the DRAM term via cache-priority
// partitioning: rows < T load evict-normal (stay L2-resident across graph
// replays, ~113MB pinned-by-pressure), rows >= T load evict-first (.cs,
// stream through L2 without evicting the resident set). idx loads and out
// stores are also .cs so they never displace the resident table half.

constexpr int K = 32;
constexpr int D = 128;
constexpr int T_ROWS = 225000;   // resident slice = 225000*512B = 115MB

__device__ __forceinline__ float4 ld_cs_f4(const float4* p) {
    float4 v;
    asm volatile("ld.global.cs.v4.f32 {%0,%1,%2,%3}, [%4];"
                 : "=f"(v.x), "=f"(v.y), "=f"(v.z), "=f"(v.w) : "l"(p));
    return v;
}
__device__ __forceinline__ void st_cs_f4(float4* p, float4 v) {
    asm volatile("st.global.cs.v4.f32 [%0], {%1,%2,%3,%4};"
                 :: "l"(p), "f"(v.x), "f"(v.y), "f"(v.z), "f"(v.w) : "memory");
}
__device__ __forceinline__ int ld_cs_i32(const int* p) {
    int v;
    asm volatile("ld.global.cs.s32 %0, [%1];" : "=r"(v) : "l"(p));
    return v;
}

__global__ __launch_bounds__(256) void mean_agg_kernel(
    const float* __restrict__ tab,
    const int*   __restrict__ idx,
    float* __restrict__ out,
    int B)
{
    int gtid = blockIdx.x * blockDim.x + threadIdx.x;
    int warp = gtid >> 5;
    int lane = gtid & 31;
    if (warp >= B) return;

    // One coalesced 4B index load per lane (streaming, read-once).
    int my_idx = ld_cs_i32(&idx[(size_t)warp * K + lane]);

    float4 acc = make_float4(0.f, 0.f, 0.f, 0.f);

    #pragma unroll
    for (int k = 0; k < K; ++k) {
        int r = __shfl_sync(0xffffffffu, my_idx, k);   // warp-uniform row
        const float4* row = reinterpret_cast<const float4*>(tab + (size_t)r * D);
        float4 v;
        if (r < T_ROWS) {
            v = __ldg(&row[lane]);       // evict-normal: stays L2-resident
        } else {
            v = ld_cs_f4(&row[lane]);    // evict-first: streams through L2
        }
        acc.x += v.x; acc.y += v.y; acc.z += v.z; acc.w += v.w;
    }

    const float s = 1.0f / (float)K;
    acc.x *= s; acc.y *= s; acc.z *= s; acc.w *= s;

    st_cs_f4(&reinterpret_cast<float4*>(out + (size_t)warp * D)[lane], acc);
}

extern "C" void kernel_launch(void* const* d_in, const int* in_sizes, int n_in,
                              void* d_out, int out_size)
{
    // Identify inputs by element count (robust to metadata ordering):
    // embed_table: 64,000,000 ; neigh_idx: 3,200,000 ; num_sample: 1
    long long max_sz = -1, mid_sz = -1;
    int ti = 0, ii = 1;
    for (int i = 0; i < n_in; ++i)
        if (in_sizes[i] > max_sz) { max_sz = in_sizes[i]; ti = i; }
    for (int i = 0; i < n_in; ++i)
        if (i != ti && in_sizes[i] > mid_sz) { mid_sz = in_sizes[i]; ii = i; }

    const float* tab = (const float*)d_in[ti];
    const int*   idx = (const int*)d_in[ii];
    float*       out = (float*)d_out;

    int B = out_size / D;                    // 100000

    int threads = 256;                       // 8 warps/block, 1 node per warp
    long long total_threads = (long long)B * 32;
    int blocks = (int)((total_threads + threads - 1) / threads);

    mean_agg_kernel<<<blocks, threads>>>(tab, idx, out, B);
}